// round 14
// baseline (speedup 1.0000x reference)
#include <cuda_runtime.h>
#include <math_constants.h>
#include <cstdint>

#define NNODES 2048
#define HID    1024
#define TSTEPS (NNODES + NNODES / 8)   // 2304
#define LDB_B  1028                    // padded leading dim for B (keeps float4 alignment)
#define MPAD   1152                    // 1026 padded up to a multiple of 128

// -------- scratch (device globals; no allocation allowed) --------
__device__ __align__(16) float g_WqT[MPAD * HID];             // Wq^T  [1026->1152, 1024]
__device__ __align__(16) float g_WkT[HID * HID];              // Wk^T  [1024,1024]
__device__ __align__(16) float g_GT [MPAD * HID];             // GT[c,i] = sum_h Wq[h,c]*Wk[h,i]
__device__ __align__(16) float g_B  [NNODES * LDB_B];         // B[k,c] = emb[k].G[:,c] + g0[c]
__device__ __align__(16) float g_ST[(size_t)NNODES * NNODES]; // ST'[l][k] = SC*(emb[l].B[k,:H] + w0[k])
__device__ __align__(16) float g_u  [NNODES];                 // u'[k] = SC * B[k,HID]
__device__ __align__(16) float g_w0 [NNODES];                 // w0[k] = emb[k].r + s0
__device__ __align__(16) float g_r  [HID + 4];                // r = Wk^T bq ; g_r[HID] = s0 = bk.bq
__device__ __align__(16) float g_g0 [MPAD];                   // g0[c] = bk . Wq[:,c]
__device__ float g_sink;                                      // DCE-blocker for the warm kernel

// ---------------------------------------------------------------------------
// Tiled fp32 GEMM (NT form): C[M,N] = scale * (A[M,K] * Bt[N,K]^T + bias[N])
// (R3 version — measured 259us on the 2048x2048x1024 tile)
// Requires: M % 128 == 0, K % 8 == 0, rows 16B-aligned. N guarded.
// ---------------------------------------------------------------------------
__global__ __launch_bounds__(256) void sgemm_nt(
    const float* __restrict__ A, int lda,
    const float* __restrict__ Bt, int ldb,
    float* __restrict__ C, int ldc,
    int M, int N, int K, const float* __restrict__ bias, float scale)
{
    __shared__ float As[8][132];
    __shared__ float Bs[8][132];

    const int tid = threadIdx.x;
    const int tx = tid % 16;          // N direction (8 cols each)
    const int ty = tid / 16;          // M direction (8 rows each)
    const int m0 = blockIdx.y * 128;
    const int n0 = blockIdx.x * 128;

    const int lrow = tid >> 1;        // 0..127
    const int lk4  = (tid & 1) * 4;   // 0 or 4

    float acc[8][8];
#pragma unroll
    for (int i = 0; i < 8; i++)
#pragma unroll
        for (int j = 0; j < 8; j++) acc[i][j] = 0.0f;

    for (int k0 = 0; k0 < K; k0 += 8) {
        float4 av = *(const float4*)(A + (size_t)(m0 + lrow) * lda + k0 + lk4);
        As[lk4 + 0][lrow] = av.x; As[lk4 + 1][lrow] = av.y;
        As[lk4 + 2][lrow] = av.z; As[lk4 + 3][lrow] = av.w;

        float4 bv = make_float4(0.f, 0.f, 0.f, 0.f);
        const int brow = n0 + lrow;
        if (brow < N)
            bv = *(const float4*)(Bt + (size_t)brow * ldb + k0 + lk4);
        Bs[lk4 + 0][lrow] = bv.x; Bs[lk4 + 1][lrow] = bv.y;
        Bs[lk4 + 2][lrow] = bv.z; Bs[lk4 + 3][lrow] = bv.w;

        __syncthreads();

#pragma unroll
        for (int kk = 0; kk < 8; kk++) {
            float4 a0 = *(const float4*)&As[kk][ty * 8];
            float4 a1 = *(const float4*)&As[kk][ty * 8 + 4];
            float4 b0 = *(const float4*)&Bs[kk][tx * 8];
            float4 b1 = *(const float4*)&Bs[kk][tx * 8 + 4];
            float a[8] = {a0.x, a0.y, a0.z, a0.w, a1.x, a1.y, a1.z, a1.w};
            float b[8] = {b0.x, b0.y, b0.z, b0.w, b1.x, b1.y, b1.z, b1.w};
#pragma unroll
            for (int i = 0; i < 8; i++)
#pragma unroll
                for (int j = 0; j < 8; j++)
                    acc[i][j] = fmaf(a[i], b[j], acc[i][j]);
        }
        __syncthreads();
    }

#pragma unroll
    for (int i = 0; i < 8; i++) {
        const int r = m0 + ty * 8 + i;
#pragma unroll
        for (int j = 0; j < 8; j++) {
            const int c = n0 + tx * 8 + j;
            if (c < N) {
                float v = acc[i][j];
                if (bias) v += bias[c];
                C[(size_t)r * ldc + c] = v * scale;
            }
        }
    }
}

// ---------------------------------------------------------------------------
// 32x32 tiled transpose: out[C][R] = in[R][C]^T
// ---------------------------------------------------------------------------
__global__ void transpose_kernel(const float* __restrict__ in, float* __restrict__ out,
                                 int R, int C)
{
    __shared__ float t[32][33];
    int c = blockIdx.x * 32 + threadIdx.x;
    int r = blockIdx.y * 32 + threadIdx.y;
    if (r < R && c < C) t[threadIdx.y][threadIdx.x] = in[(size_t)r * C + c];
    __syncthreads();
    int oc   = blockIdx.y * 32 + threadIdx.x;
    int orow = blockIdx.x * 32 + threadIdx.y;
    if (orow < C && oc < R) out[(size_t)orow * R + oc] = t[threadIdx.x][threadIdx.y];
}

// ---------------------------------------------------------------------------
// r[i] = sum_h Wk[h,i]*bq[h]  (blocks 0..3; coalesced column dots)
// s0   = bk . bq -> g_r[HID]  (block 4)
// ---------------------------------------------------------------------------
__global__ __launch_bounds__(256) void rs_kernel(
    const float* __restrict__ Wk, const float* __restrict__ bq,
    const float* __restrict__ bk)
{
    if (blockIdx.x < 4) {
        int i = blockIdx.x * 256 + threadIdx.x;   // 0..1023
        float s = 0.0f;
        for (int h = 0; h < HID; h++)
            s = fmaf(Wk[(size_t)h * HID + i], bq[h], s);
        g_r[i] = s;
    } else {
        __shared__ float red[256];
        float s = 0.0f;
        for (int h = threadIdx.x; h < HID; h += 256)
            s = fmaf(bk[h], bq[h], s);
        red[threadIdx.x] = s;
        __syncthreads();
        for (int o = 128; o > 0; o >>= 1) {
            if (threadIdx.x < o) red[threadIdx.x] += red[threadIdx.x + o];
            __syncthreads();
        }
        if (threadIdx.x == 0) g_r[HID] = red[0];
    }
}

// ---------------------------------------------------------------------------
// g0[c] = sum_h bk[h] * Wq[h,c]   (coalesced: consecutive c contiguous)
// ---------------------------------------------------------------------------
__global__ __launch_bounds__(256) void g0_kernel(
    const float* __restrict__ Wq, const float* __restrict__ bk)
{
    int c = blockIdx.x * 256 + threadIdx.x;
    if (c >= HID + 2) return;
    float s = 0.0f;
    for (int h = 0; h < HID; h++)
        s = fmaf(bk[h], Wq[(size_t)h * (HID + 2) + c], s);
    g_g0[c] = s;
}

// ---------------------------------------------------------------------------
// w0[k] = emb[k].r + s0 ; u'[k] = SC * B[k,HID]    (one warp per k)
// ---------------------------------------------------------------------------
__global__ __launch_bounds__(256) void w0u_kernel(const float* __restrict__ emb)
{
    const float SC = 0.015625f;  // ALPHA / sqrt(HID) = 0.5/32 (exact pow2)
    int k = blockIdx.x * 8 + (threadIdx.x >> 5);
    int lane = threadIdx.x & 31;
    if (k >= NNODES) return;
    float s = 0.0f;
    const float* erow = emb + (size_t)k * HID;
    for (int j = lane; j < HID; j += 32) s = fmaf(erow[j], g_r[j], s);
#pragma unroll
    for (int o = 16; o > 0; o >>= 1) s += __shfl_down_sync(0xffffffffu, s, o);
    if (lane == 0) {
        g_w0[k] = s + g_r[HID];
        g_u[k]  = g_B[(size_t)k * LDB_B + HID] * SC;
    }
}

// ---------------------------------------------------------------------------
// L2-warm: stream all of ST through L2 right before decode (measured WIN R10:
// turns decode row loads from DRAM misses ~577cy into L2 hits ~250cy).
// ---------------------------------------------------------------------------
__global__ __launch_bounds__(256) void warm_l2_kernel()
{
    const float4* p = (const float4*)g_ST;
    const int n4 = (NNODES * NNODES) / 4;
    float s = 0.0f;
    for (int i = blockIdx.x * blockDim.x + threadIdx.x; i < n4;
         i += gridDim.x * blockDim.x) {
        float4 v = p[i];
        s += v.x + v.y + v.z + v.w;
    }
    if (s == 1.23456789e30f) g_sink = s;   // never true; blocks DCE
}

// monotone float -> orderable uint (bijective, order-preserving incl. +-inf)
__device__ __forceinline__ unsigned mapf(float f) {
    unsigned u = __float_as_uint(f);
    return u ^ (((unsigned)((int)u >> 31)) | 0x80000000u);
}
// inverse of mapf, returned as raw float bit pattern
__device__ __forceinline__ unsigned unmapf(unsigned v) {
    return (v & 0x80000000u) ? (v ^ 0x80000000u) : ~v;
}

// ---------------------------------------------------------------------------
// Sequential greedy decode. Single CTA, 256 threads (8 warps), 8 nodes/thread.
// Per-warp winner (value,minidx) packed as 64-bit key; ONE barrier per step
// via parity double-buffered smem exchange. (Correctness-validated in R9 bench.)
// Output (float32): out[0..TSTEPS] = tour, out[TSTEPS+1 .. 2*TSTEPS] = scores.
// ---------------------------------------------------------------------------
__global__ __launch_bounds__(256) void decode_kernel(
    const float* __restrict__ demands,
    const int* __restrict__ cap_p,
    const int* __restrict__ depot_p,
    float* __restrict__ out)
{
    __shared__ __align__(16) float dem_s[NNODES];
    __shared__ __align__(16) unsigned long long wkey[2][8];   // [parity][warp]

    const int t    = threadIdx.x;      // 0..255
    const int lane = t & 31;
    const int wid  = t >> 5;           // 0..7

    const float capf    = (float)(*cap_p);
    const float inv_cap = 1.0f / capf;
    const int   depot   = *depot_p;

    for (int i = t; i < NNODES / 4; i += 256)
        ((float4*)dem_s)[i] = ((const float4*)demands)[i];

    // thread owns nodes k = 1024*i + 4*t + c,  i in 0..1, c in 0..3
    float4 u4[2];
    u4[0] = ((const float4*)g_u)[t];
    u4[1] = ((const float4*)g_u)[256 + t];
    __syncthreads();
    float4 dm4[2];
    dm4[0] = ((const float4*)dem_s)[t];
    dm4[1] = ((const float4*)dem_s)[256 + t];

    unsigned vis = 0;                  // bit (i*4 + c)
    if (((depot >> 2) & 255) == t) vis |= 1u << (((depot >> 10) << 2) + (depot & 3));
    if (t == 0) out[0] = (float)depot;

    float loadv  = capf;
    int   last   = depot;
    int   done   = 0;
    int   vcount = 1;                  // depot pre-visited

    for (int step = 0; step < TSTEPS; step++) {
        const int p = step & 1;
        const float4* row = (const float4*)(g_ST + (size_t)last * NNODES);
        float4 st0 = row[t];
        float4 st1 = row[256 + t];

        const float lf = loadv * inv_cap;

        // masked scores for the 8 owned nodes
        float m[8];
        {
            const float* sp = (const float*)&st0;
            const float* up = (const float*)&u4[0];
            const float* dp = (const float*)&dm4[0];
#pragma unroll
            for (int c = 0; c < 4; c++) {
                float s = fmaf(up[c], lf, sp[c]);
                bool feas = (((vis >> c) & 1u) == 0u) && (dp[c] <= loadv);
                m[c] = feas ? s : -CUDART_INF_F;
            }
        }
        {
            const float* sp = (const float*)&st1;
            const float* up = (const float*)&u4[1];
            const float* dp = (const float*)&dm4[1];
#pragma unroll
            for (int c = 0; c < 4; c++) {
                float s = fmaf(up[c], lf, sp[c]);
                bool feas = (((vis >> (4 + c)) & 1u) == 0u) && (dp[c] <= loadv);
                m[4 + c] = feas ? s : -CUDART_INF_F;
            }
        }

        // local value max (balanced tree)
        float a0 = fmaxf(m[0], m[4]), a1 = fmaxf(m[1], m[5]);
        float a2 = fmaxf(m[2], m[6]), a3 = fmaxf(m[3], m[7]);
        float lmax = fmaxf(fmaxf(a0, a1), fmaxf(a2, a3));

        // per-warp value winner
        unsigned wmax = __reduce_max_sync(0xffffffffu, mapf(lmax));
        const unsigned wraw = unmapf(wmax);

        // per-warp min index matching the warp winner value
        int li = 0x7fffffff;
#pragma unroll
        for (int i = 0; i < 2; i++)
#pragma unroll
            for (int c = 0; c < 4; c++) {
                int k = 1024 * i + 4 * t + c;
                int cand = (__float_as_uint(m[i * 4 + c]) == wraw) ? k : 0x7fffffff;
                li = min(li, cand);
            }
        unsigned wmin = __reduce_min_sync(0xffffffffu, (unsigned)li);

        if (lane == 0)
            wkey[p][wid] = ((unsigned long long)wmax << 32) | (unsigned)(~wmin);
        __syncthreads();   // the ONLY barrier per step (parity buffer kills the WAR)

        // merge 8 warp keys: 64-bit max == lexicographic (max value, min index)
        const ulonglong2 k01 = ((const ulonglong2*)wkey[p])[0];
        const ulonglong2 k23 = ((const ulonglong2*)wkey[p])[1];
        const ulonglong2 k45 = ((const ulonglong2*)wkey[p])[2];
        const ulonglong2 k67 = ((const ulonglong2*)wkey[p])[3];
        unsigned long long b0 = max(k01.x, k01.y), b1 = max(k23.x, k23.y);
        unsigned long long b2 = max(k45.x, k45.y), b3 = max(k67.x, k67.y);
        unsigned long long bestk = max(max(b0, b1), max(b2, b3));

        const unsigned gbits = unmapf((unsigned)(bestk >> 32));
        const float bv = __uint_as_float(gbits);
        const int   bi = (int)~((unsigned)bestk);

        const int take = (bv != -CUDART_INF_F) && !done;
        const int nxt  = take ? bi : depot;

        if (t == 0) {
            out[1 + step]            = (float)nxt;
            out[(TSTEPS + 1) + step] = take ? bv : 0.0f;
        }

        if (take) {
            if (((bi >> 2) & 255) == t) vis |= 1u << (((bi >> 10) << 2) + (bi & 3));
            loadv = loadv - dem_s[bi];
            vcount++;
        } else {
            loadv = capf;
        }
        done = done || (!take && vcount == NNODES);
        last = nxt;

        if (done) {
            // remaining steps are pure padding: depot / score 0
            const float df = (float)depot;
            for (int j = step + 1 + t; j < TSTEPS; j += 256) {
                out[1 + j]            = df;
                out[(TSTEPS + 1) + j] = 0.0f;
            }
            break;
        }
    }
}

// ---------------------------------------------------------------------------
extern "C" void kernel_launch(void* const* d_in, const int* in_sizes, int n_in,
                              void* d_out, int out_size)
{
    const float* node_emb = (const float*)d_in[0];   // [2048,1024]
    const float* demands  = (const float*)d_in[1];   // [2048]
    const float* Wq       = (const float*)d_in[2];   // [1024,1026]
    const float* bq       = (const float*)d_in[3];   // [1024]
    const float* Wk       = (const float*)d_in[4];   // [1024,1024]
    const float* bk       = (const float*)d_in[5];   // [1024]
    const int*   cap_p    = (const int*)d_in[6];     // scalar 40
    const int*   depot_p  = (const int*)d_in[7];     // scalar 0
    float* out = (float*)d_out;

    const float SC = 0.015625f;  // ALPHA / sqrt(HID)

    void *pWqT, *pWkT, *pGT, *pB, *pST, *pW0, *pG0;
    cudaGetSymbolAddress(&pWqT, g_WqT);
    cudaGetSymbolAddress(&pWkT, g_WkT);
    cudaGetSymbolAddress(&pGT,  g_GT);
    cudaGetSymbolAddress(&pB,   g_B);
    cudaGetSymbolAddress(&pST,  g_ST);
    cudaGetSymbolAddress(&pW0,  g_w0);
    cudaGetSymbolAddress(&pG0,  g_g0);

    // 1) WqT = Wq^T  [1026,1024] (rows 1026..1151 of the padded buffer unused/garbage)
    transpose_kernel<<<dim3((HID + 2 + 31) / 32, (HID + 31) / 32), dim3(32, 32)>>>(
        Wq, (float*)pWqT, HID, HID + 2);

    // 2) WkT = Wk^T  [1024,1024]
    transpose_kernel<<<dim3(HID / 32, HID / 32), dim3(32, 32)>>>(
        Wk, (float*)pWkT, HID, HID);

    // 3) GT[c,i] = sum_h Wq[h,c]*Wk[h,i]   (M padded to 1152; junk rows never read)
    sgemm_nt<<<dim3(HID / 128, MPAD / 128), 256>>>(
        (const float*)pWqT, HID, (const float*)pWkT, HID,
        (float*)pGT, HID, MPAD, HID, HID, nullptr, 1.0f);

    // 4) r = Wk^T bq ; s0 = bk.bq
    rs_kernel<<<5, 256>>>(Wk, bq, bk);

    // 5) g0[c] = bk . Wq[:,c]
    g0_kernel<<<(HID + 2 + 255) / 256, 256>>>(Wq, bk);

    // 6) B = emb @ G + g0   ([2048,1026], ld 1028)  — replaces K GEMM + B GEMM
    sgemm_nt<<<dim3((HID + 2 + 127) / 128, NNODES / 128), 256>>>(
        node_emb, HID, (const float*)pGT, HID,
        (float*)pB, LDB_B, NNODES, HID + 2, HID, (const float*)pG0, 1.0f);

    // 7) w0[k] = emb[k].r + s0 ; u'[k] = SC*B[k,HID]
    w0u_kernel<<<NNODES / 8, 256>>>(node_emb);

    // 8) ST' = SC * (emb @ B[:, :H]^T + w0)   ([2048,2048])
    sgemm_nt<<<dim3(NNODES / 128, NNODES / 128), 256>>>(
        node_emb, HID, (const float*)pB, LDB_B,
        (float*)pST, NNODES, NNODES, NNODES, HID, (const float*)pW0, SC);

    // 9) re-stream ST through L2 so decode's row loads are L2 hits (R10 WIN)
    warm_l2_kernel<<<2048, 256>>>();

    // 10) sequential decode (single CTA, 8 warps, one barrier/step)
    decode_kernel<<<1, 256>>>(demands, cap_p, depot_p, out);
}

// round 15
// speedup vs baseline: 1.7321x; 1.7321x over previous
#include <cuda_runtime.h>
#include <math_constants.h>
#include <cstdint>

#define NNODES 2048
#define HID    1024
#define TSTEPS (NNODES + NNODES / 8)   // 2304
#define LDB_B  1028                    // padded leading dim for B (keeps float4 alignment)

// -------- scratch (device globals; no allocation allowed) --------
__device__ __align__(16) float g_K [NNODES * HID];            // K = node_emb @ Wk^T + bk   [2048,1024]
__device__ __align__(16) float g_WqT[(HID + 2) * HID];        // Wq^T                       [1026,1024]
__device__ __align__(16) float g_B [NNODES * LDB_B];          // B = K @ Wq                 [2048,1026]
__device__ __align__(16) float g_ST[(size_t)NNODES * NNODES]; // ST'[l][k] = SC*(emb[l].B[k,:H] + w0[k])
__device__ __align__(16) float g_u [NNODES];                  // u'[k] = SC * B[k,HID]
__device__ __align__(16) float g_w0[NNODES];                  // w0[k] = K[k,:] . bq
__device__ float g_sink;                                      // DCE-blocker for the warm kernel

// ---------------------------------------------------------------------------
// Tiled fp32 GEMM (NT form): C[M,N] = scale * (A[M,K] * Bt[N,K]^T + bias[N])
// (R3 version — measured 259us on the 2048x2048x1024 tile)
// Requires: M % 128 == 0, K % 8 == 0, rows 16B-aligned. N guarded.
// ---------------------------------------------------------------------------
__global__ __launch_bounds__(256) void sgemm_nt(
    const float* __restrict__ A, int lda,
    const float* __restrict__ Bt, int ldb,
    float* __restrict__ C, int ldc,
    int M, int N, int K, const float* __restrict__ bias, float scale)
{
    __shared__ float As[8][132];
    __shared__ float Bs[8][132];

    const int tid = threadIdx.x;
    const int tx = tid % 16;          // N direction (8 cols each)
    const int ty = tid / 16;          // M direction (8 rows each)
    const int m0 = blockIdx.y * 128;
    const int n0 = blockIdx.x * 128;

    const int lrow = tid >> 1;        // 0..127
    const int lk4  = (tid & 1) * 4;   // 0 or 4

    float acc[8][8];
#pragma unroll
    for (int i = 0; i < 8; i++)
#pragma unroll
        for (int j = 0; j < 8; j++) acc[i][j] = 0.0f;

    for (int k0 = 0; k0 < K; k0 += 8) {
        float4 av = *(const float4*)(A + (size_t)(m0 + lrow) * lda + k0 + lk4);
        As[lk4 + 0][lrow] = av.x; As[lk4 + 1][lrow] = av.y;
        As[lk4 + 2][lrow] = av.z; As[lk4 + 3][lrow] = av.w;

        float4 bv = make_float4(0.f, 0.f, 0.f, 0.f);
        const int brow = n0 + lrow;
        if (brow < N)
            bv = *(const float4*)(Bt + (size_t)brow * ldb + k0 + lk4);
        Bs[lk4 + 0][lrow] = bv.x; Bs[lk4 + 1][lrow] = bv.y;
        Bs[lk4 + 2][lrow] = bv.z; Bs[lk4 + 3][lrow] = bv.w;

        __syncthreads();

#pragma unroll
        for (int kk = 0; kk < 8; kk++) {
            float4 a0 = *(const float4*)&As[kk][ty * 8];
            float4 a1 = *(const float4*)&As[kk][ty * 8 + 4];
            float4 b0 = *(const float4*)&Bs[kk][tx * 8];
            float4 b1 = *(const float4*)&Bs[kk][tx * 8 + 4];
            float a[8] = {a0.x, a0.y, a0.z, a0.w, a1.x, a1.y, a1.z, a1.w};
            float b[8] = {b0.x, b0.y, b0.z, b0.w, b1.x, b1.y, b1.z, b1.w};
#pragma unroll
            for (int i = 0; i < 8; i++)
#pragma unroll
                for (int j = 0; j < 8; j++)
                    acc[i][j] = fmaf(a[i], b[j], acc[i][j]);
        }
        __syncthreads();
    }

#pragma unroll
    for (int i = 0; i < 8; i++) {
        const int r = m0 + ty * 8 + i;
#pragma unroll
        for (int j = 0; j < 8; j++) {
            const int c = n0 + tx * 8 + j;
            if (c < N) {
                float v = acc[i][j];
                if (bias) v += bias[c];
                C[(size_t)r * ldc + c] = v * scale;
            }
        }
    }
}

// ---------------------------------------------------------------------------
// 32x32 tiled transpose: out[C][R] = in[R][C]^T
// ---------------------------------------------------------------------------
__global__ void transpose_kernel(const float* __restrict__ in, float* __restrict__ out,
                                 int R, int C)
{
    __shared__ float t[32][33];
    int c = blockIdx.x * 32 + threadIdx.x;
    int r = blockIdx.y * 32 + threadIdx.y;
    if (r < R && c < C) t[threadIdx.y][threadIdx.x] = in[(size_t)r * C + c];
    __syncthreads();
    int oc   = blockIdx.y * 32 + threadIdx.x;
    int orow = blockIdx.x * 32 + threadIdx.y;
    if (orow < C && oc < R) out[(size_t)orow * R + oc] = t[threadIdx.x][threadIdx.y];
}

// ---------------------------------------------------------------------------
// w0[k] = K[k,:] . bq ; u'[k] = SC * B[k, HID]   (one warp per k)
// ---------------------------------------------------------------------------
__global__ void uw_kernel(const float* __restrict__ bq)
{
    const float SC = 0.015625f;  // ALPHA / sqrt(HID) = 0.5/32 (exact pow2)
    int k = blockIdx.x * 8 + (threadIdx.x >> 5);
    int lane = threadIdx.x & 31;
    if (k >= NNODES) return;
    float s = 0.0f;
    const float* krow = g_K + (size_t)k * HID;
    for (int j = lane; j < HID; j += 32) s = fmaf(krow[j], bq[j], s);
#pragma unroll
    for (int o = 16; o > 0; o >>= 1) s += __shfl_down_sync(0xffffffffu, s, o);
    if (lane == 0) {
        g_w0[k] = s;
        g_u[k]  = g_B[(size_t)k * LDB_B + HID] * SC;
    }
}

// ---------------------------------------------------------------------------
// L2-warm: stream all of ST through L2 right before decode (measured WIN R10:
// turns decode row loads from DRAM misses ~577cy into L2 hits ~250cy).
// ---------------------------------------------------------------------------
__global__ __launch_bounds__(256) void warm_l2_kernel()
{
    const float4* p = (const float4*)g_ST;
    const int n4 = (NNODES * NNODES) / 4;
    float s = 0.0f;
    for (int i = blockIdx.x * blockDim.x + threadIdx.x; i < n4;
         i += gridDim.x * blockDim.x) {
        float4 v = p[i];
        s += v.x + v.y + v.z + v.w;
    }
    if (s == 1.23456789e30f) g_sink = s;   // never true; blocks DCE
}

// monotone float -> orderable uint (bijective, order-preserving incl. +-inf)
__device__ __forceinline__ unsigned mapf(float f) {
    unsigned u = __float_as_uint(f);
    return u ^ (((unsigned)((int)u >> 31)) | 0x80000000u);
}
// inverse of mapf, returned as raw float bit pattern
__device__ __forceinline__ unsigned unmapf(unsigned v) {
    return (v & 0x80000000u) ? (v ^ 0x80000000u) : ~v;
}

// ---------------------------------------------------------------------------
// Sequential greedy decode. Single CTA, 128 threads (4 warps), 16 nodes/thread.
// R10 structure, but the per-warp winner (value,minidx) is packed as a 64-bit
// key and exchanged through parity-double-buffered smem: ONE barrier per step
// (packing/parity validated in R6/R9; 128-thr ownership + redux validated R10).
// Output (float32): out[0..TSTEPS] = tour, out[TSTEPS+1 .. 2*TSTEPS] = scores.
// ---------------------------------------------------------------------------
__global__ __launch_bounds__(128) void decode_kernel(
    const float* __restrict__ demands,
    const int* __restrict__ cap_p,
    const int* __restrict__ depot_p,
    float* __restrict__ out)
{
    __shared__ __align__(16) float dem_s[NNODES];
    __shared__ __align__(16) unsigned long long wkey[2][4];   // [parity][warp]

    const int t    = threadIdx.x;      // 0..127
    const int lane = t & 31;
    const int wid  = t >> 5;           // 0..3

    const float capf    = (float)(*cap_p);
    const float inv_cap = 1.0f / capf;
    const int   depot   = *depot_p;

    for (int i = t; i < NNODES / 4; i += 128)
        ((float4*)dem_s)[i] = ((const float4*)demands)[i];

    // thread owns nodes k = (i*128 + t)*4 + c,  i in 0..3, c in 0..3
    float4 u4[4];
#pragma unroll
    for (int i = 0; i < 4; i++)
        u4[i] = ((const float4*)g_u)[i * 128 + t];
    __syncthreads();
    float4 dm4[4];
#pragma unroll
    for (int i = 0; i < 4; i++)
        dm4[i] = ((const float4*)dem_s)[i * 128 + t];

    unsigned vis = 0;                  // bit (i*4+c)
    if (((depot >> 2) & 127) == t) vis |= 1u << (((depot >> 9) << 2) + (depot & 3));
    if (t == 0) out[0] = (float)depot;

    float loadv  = capf;
    int   last   = depot;
    int   done   = 0;
    int   vcount = 1;

    for (int step = 0; step < TSTEPS; step++) {
        const int p = step & 1;
        const float4* row = (const float4*)(g_ST + (size_t)last * NNODES);
        float4 st[4];
#pragma unroll
        for (int i = 0; i < 4; i++) st[i] = row[i * 128 + t];

        const float lf = loadv * inv_cap;

        // masked scores for the 16 owned nodes
        float m[16];
#pragma unroll
        for (int i = 0; i < 4; i++) {
            const float* sp = (const float*)&st[i];
            const float* up = (const float*)&u4[i];
            const float* dp = (const float*)&dm4[i];
#pragma unroll
            for (int c = 0; c < 4; c++) {
                float s = fmaf(up[c], lf, sp[c]);
                bool feas = (((vis >> (i * 4 + c)) & 1u) == 0u) && (dp[c] <= loadv);
                m[i * 4 + c] = feas ? s : -CUDART_INF_F;
            }
        }

        // local value max (balanced fmax tree)
        float p8[8];
#pragma unroll
        for (int i = 0; i < 8; i++) p8[i] = fmaxf(m[i], m[i + 8]);
        float p4a = fmaxf(p8[0], p8[4]), p4b = fmaxf(p8[1], p8[5]);
        float p4c = fmaxf(p8[2], p8[6]), p4d = fmaxf(p8[3], p8[7]);
        float lmax = fmaxf(fmaxf(p4a, p4b), fmaxf(p4c, p4d));

        // per-warp value winner
        unsigned wmax = __reduce_max_sync(0xffffffffu, mapf(lmax));
        const unsigned wraw = unmapf(wmax);

        // per-warp min index matching the warp winner value
        int li = 0x7fffffff;
#pragma unroll
        for (int i = 0; i < 4; i++)
#pragma unroll
            for (int c = 0; c < 4; c++) {
                int k = ((i * 128 + t) << 2) + c;
                int cand = (__float_as_uint(m[i * 4 + c]) == wraw) ? k : 0x7fffffff;
                li = min(li, cand);
            }
        unsigned wmin = __reduce_min_sync(0xffffffffu, (unsigned)li);

        if (lane == 0)
            wkey[p][wid] = ((unsigned long long)wmax << 32) | (unsigned)(~wmin);
        __syncthreads();   // the ONLY barrier per step (parity buffer kills the WAR)

        // merge 4 warp keys: 64-bit max == lexicographic (max value, min index)
        const ulonglong2 k01 = ((const ulonglong2*)wkey[p])[0];
        const ulonglong2 k23 = ((const ulonglong2*)wkey[p])[1];
        unsigned long long bestk = max(max(k01.x, k01.y), max(k23.x, k23.y));

        const unsigned gbits = unmapf((unsigned)(bestk >> 32));
        const float bv = __uint_as_float(gbits);
        const int   bi = (int)~((unsigned)bestk);

        const int take = (bv != -CUDART_INF_F) && !done;
        const int nxt  = take ? bi : depot;

        if (t == 0) {
            out[1 + step]            = (float)nxt;
            out[(TSTEPS + 1) + step] = take ? bv : 0.0f;
        }

        if (take) {
            if (((bi >> 2) & 127) == t) vis |= 1u << (((bi >> 9) << 2) + (bi & 3));
            loadv = loadv - dem_s[bi];
            vcount++;
        } else {
            loadv = capf;
        }
        done = done || (!take && vcount == NNODES);
        last = nxt;

        if (done) {
            // remaining steps are pure padding: depot / score 0
            const float df = (float)depot;
            for (int j = step + 1 + t; j < TSTEPS; j += 128) {
                out[1 + j]            = df;
                out[(TSTEPS + 1) + j] = 0.0f;
            }
            break;
        }
    }
}

// ---------------------------------------------------------------------------
extern "C" void kernel_launch(void* const* d_in, const int* in_sizes, int n_in,
                              void* d_out, int out_size)
{
    const float* node_emb = (const float*)d_in[0];   // [2048,1024]
    const float* demands  = (const float*)d_in[1];   // [2048]
    const float* Wq       = (const float*)d_in[2];   // [1024,1026]
    const float* bq       = (const float*)d_in[3];   // [1024]
    const float* Wk       = (const float*)d_in[4];   // [1024,1024]
    const float* bk       = (const float*)d_in[5];   // [1024]
    const int*   cap_p    = (const int*)d_in[6];     // scalar 40
    const int*   depot_p  = (const int*)d_in[7];     // scalar 0
    float* out = (float*)d_out;

    const float SC = 0.015625f;  // ALPHA / sqrt(HID)

    void *pK, *pWqT, *pB, *pST, *pW0;
    cudaGetSymbolAddress(&pK,   g_K);
    cudaGetSymbolAddress(&pWqT, g_WqT);
    cudaGetSymbolAddress(&pB,   g_B);
    cudaGetSymbolAddress(&pST,  g_ST);
    cudaGetSymbolAddress(&pW0,  g_w0);

    // 1) K = node_emb @ Wk^T + bk
    sgemm_nt<<<dim3(HID / 128, NNODES / 128), 256>>>(
        node_emb, HID, Wk, HID, (float*)pK, HID, NNODES, HID, HID, bk, 1.0f);

    // 2) WqT = Wq^T
    transpose_kernel<<<dim3((HID + 2 + 31) / 32, (HID + 31) / 32), dim3(32, 32)>>>(
        Wq, (float*)pWqT, HID, HID + 2);

    // 3) B = K @ Wq   ([2048,1026], ld 1028)
    sgemm_nt<<<dim3((HID + 2 + 127) / 128, NNODES / 128), 256>>>(
        (const float*)pK, HID, (const float*)pWqT, HID,
        (float*)pB, LDB_B, NNODES, HID + 2, HID, nullptr, 1.0f);

    // 4) w0 = K @ bq ; u' = SC * B[:,HID]
    uw_kernel<<<NNODES / 8, 256>>>(bq);

    // 5) ST' = SC * (node_emb @ B[:, :HID]^T + w0)   ([2048,2048])
    sgemm_nt<<<dim3(NNODES / 128, NNODES / 128), 256>>>(
        node_emb, HID, (const float*)pB, LDB_B,
        (float*)pST, NNODES, NNODES, NNODES, HID, (const float*)pW0, SC);

    // 6) re-stream ST through L2 so decode's row loads are L2 hits (R10 WIN)
    warm_l2_kernel<<<2048, 256>>>();

    // 7) sequential decode (single CTA, 4 warps, ONE barrier per step)
    decode_kernel<<<1, 128>>>(demands, cap_p, depot_p, out);
}

// round 16
// speedup vs baseline: 1.8704x; 1.0799x over previous
#include <cuda_runtime.h>
#include <math_constants.h>
#include <cstdint>

#define NNODES 2048
#define HID    1024
#define TSTEPS (NNODES + NNODES / 8)   // 2304
#define LDB_B  1028                    // padded leading dim for B (keeps float4 alignment)

// -------- scratch (device globals; no allocation allowed) --------
__device__ __align__(16) float g_K [NNODES * HID];            // K = node_emb @ Wk^T + bk   [2048,1024]
__device__ __align__(16) float g_WqT[(HID + 2) * HID];        // Wq^T                       [1026,1024]
__device__ __align__(16) float g_B [NNODES * LDB_B];          // B = K @ Wq                 [2048,1026]
__device__ __align__(16) float g_ST[(size_t)NNODES * NNODES]; // ST'[l][k] = SC*(emb[l].B[k,:H] + w0[k])
__device__ __align__(16) float g_u [NNODES];                  // u'[k] = SC * B[k,HID]
__device__ __align__(16) float g_w0[NNODES];                  // w0[k] = K[k,:] . bq
__device__ float g_sink;                                      // DCE-blocker for the warm kernel

// ---------------------------------------------------------------------------
// Tiled fp32 GEMM (NT form): C[M,N] = scale * (A[M,K] * Bt[N,K]^T + bias[N])
// (R3 version — measured 259us on the 2048x2048x1024 tile)
// Requires: M % 128 == 0, K % 8 == 0, rows 16B-aligned. N guarded.
// ---------------------------------------------------------------------------
__global__ __launch_bounds__(256) void sgemm_nt(
    const float* __restrict__ A, int lda,
    const float* __restrict__ Bt, int ldb,
    float* __restrict__ C, int ldc,
    int M, int N, int K, const float* __restrict__ bias, float scale)
{
    __shared__ float As[8][132];
    __shared__ float Bs[8][132];

    const int tid = threadIdx.x;
    const int tx = tid % 16;          // N direction (8 cols each)
    const int ty = tid / 16;          // M direction (8 rows each)
    const int m0 = blockIdx.y * 128;
    const int n0 = blockIdx.x * 128;

    const int lrow = tid >> 1;        // 0..127
    const int lk4  = (tid & 1) * 4;   // 0 or 4

    float acc[8][8];
#pragma unroll
    for (int i = 0; i < 8; i++)
#pragma unroll
        for (int j = 0; j < 8; j++) acc[i][j] = 0.0f;

    for (int k0 = 0; k0 < K; k0 += 8) {
        float4 av = *(const float4*)(A + (size_t)(m0 + lrow) * lda + k0 + lk4);
        As[lk4 + 0][lrow] = av.x; As[lk4 + 1][lrow] = av.y;
        As[lk4 + 2][lrow] = av.z; As[lk4 + 3][lrow] = av.w;

        float4 bv = make_float4(0.f, 0.f, 0.f, 0.f);
        const int brow = n0 + lrow;
        if (brow < N)
            bv = *(const float4*)(Bt + (size_t)brow * ldb + k0 + lk4);
        Bs[lk4 + 0][lrow] = bv.x; Bs[lk4 + 1][lrow] = bv.y;
        Bs[lk4 + 2][lrow] = bv.z; Bs[lk4 + 3][lrow] = bv.w;

        __syncthreads();

#pragma unroll
        for (int kk = 0; kk < 8; kk++) {
            float4 a0 = *(const float4*)&As[kk][ty * 8];
            float4 a1 = *(const float4*)&As[kk][ty * 8 + 4];
            float4 b0 = *(const float4*)&Bs[kk][tx * 8];
            float4 b1 = *(const float4*)&Bs[kk][tx * 8 + 4];
            float a[8] = {a0.x, a0.y, a0.z, a0.w, a1.x, a1.y, a1.z, a1.w};
            float b[8] = {b0.x, b0.y, b0.z, b0.w, b1.x, b1.y, b1.z, b1.w};
#pragma unroll
            for (int i = 0; i < 8; i++)
#pragma unroll
                for (int j = 0; j < 8; j++)
                    acc[i][j] = fmaf(a[i], b[j], acc[i][j]);
        }
        __syncthreads();
    }

#pragma unroll
    for (int i = 0; i < 8; i++) {
        const int r = m0 + ty * 8 + i;
#pragma unroll
        for (int j = 0; j < 8; j++) {
            const int c = n0 + tx * 8 + j;
            if (c < N) {
                float v = acc[i][j];
                if (bias) v += bias[c];
                C[(size_t)r * ldc + c] = v * scale;
            }
        }
    }
}

// ---------------------------------------------------------------------------
// 32x32 tiled transpose: out[C][R] = in[R][C]^T
// ---------------------------------------------------------------------------
__global__ void transpose_kernel(const float* __restrict__ in, float* __restrict__ out,
                                 int R, int C)
{
    __shared__ float t[32][33];
    int c = blockIdx.x * 32 + threadIdx.x;
    int r = blockIdx.y * 32 + threadIdx.y;
    if (r < R && c < C) t[threadIdx.y][threadIdx.x] = in[(size_t)r * C + c];
    __syncthreads();
    int oc   = blockIdx.y * 32 + threadIdx.x;
    int orow = blockIdx.x * 32 + threadIdx.y;
    if (orow < C && oc < R) out[(size_t)orow * R + oc] = t[threadIdx.x][threadIdx.y];
}

// ---------------------------------------------------------------------------
// w0[k] = K[k,:] . bq ; u'[k] = SC * B[k, HID]   (one warp per k)
// ---------------------------------------------------------------------------
__global__ void uw_kernel(const float* __restrict__ bq)
{
    const float SC = 0.015625f;  // ALPHA / sqrt(HID) = 0.5/32 (exact pow2)
    int k = blockIdx.x * 8 + (threadIdx.x >> 5);
    int lane = threadIdx.x & 31;
    if (k >= NNODES) return;
    float s = 0.0f;
    const float* krow = g_K + (size_t)k * HID;
    for (int j = lane; j < HID; j += 32) s = fmaf(krow[j], bq[j], s);
#pragma unroll
    for (int o = 16; o > 0; o >>= 1) s += __shfl_down_sync(0xffffffffu, s, o);
    if (lane == 0) {
        g_w0[k] = s;
        g_u[k]  = g_B[(size_t)k * LDB_B + HID] * SC;
    }
}

// ---------------------------------------------------------------------------
// L2-warm: stream all of ST through L2 right before decode (measured WIN R10:
// turns decode row loads from DRAM misses ~577cy into L2 hits ~250cy).
// ---------------------------------------------------------------------------
__global__ __launch_bounds__(256) void warm_l2_kernel()
{
    const float4* p = (const float4*)g_ST;
    const int n4 = (NNODES * NNODES) / 4;
    float s = 0.0f;
    for (int i = blockIdx.x * blockDim.x + threadIdx.x; i < n4;
         i += gridDim.x * blockDim.x) {
        float4 v = p[i];
        s += v.x + v.y + v.z + v.w;
    }
    if (s == 1.23456789e30f) g_sink = s;   // never true; blocks DCE
}

// monotone float -> orderable uint (bijective, order-preserving incl. +-inf)
__device__ __forceinline__ unsigned mapf(float f) {
    unsigned u = __float_as_uint(f);
    return u ^ (((unsigned)((int)u >> 31)) | 0x80000000u);
}
// inverse of mapf, returned as raw float bit pattern
__device__ __forceinline__ unsigned unmapf(unsigned v) {
    return (v & 0x80000000u) ? (v ^ 0x80000000u) : ~v;
}

// ---------------------------------------------------------------------------
// Sequential greedy decode. Single CTA, 128 threads (4 warps), 16 nodes/thread.
// One barrier per step (parity-keyed smem exchange). THIS ROUND: the row load
// for step s+1 is issued IMMEDIATELY after the merge produces `nxt`, so all
// state updates (out STGs, vis, dem LDS -> loadv, done logic) run under the
// ~250cy L2 load shadow instead of in front of it.
// Output (float32): out[0..TSTEPS] = tour, out[TSTEPS+1 .. 2*TSTEPS] = scores.
// ---------------------------------------------------------------------------
__global__ __launch_bounds__(128) void decode_kernel(
    const float* __restrict__ demands,
    const int* __restrict__ cap_p,
    const int* __restrict__ depot_p,
    float* __restrict__ out)
{
    __shared__ __align__(16) float dem_s[NNODES];
    __shared__ __align__(16) unsigned long long wkey[2][4];   // [parity][warp]

    const int t    = threadIdx.x;      // 0..127
    const int lane = t & 31;
    const int wid  = t >> 5;           // 0..3

    const float capf    = (float)(*cap_p);
    const float inv_cap = 1.0f / capf;
    const int   depot   = *depot_p;

    for (int i = t; i < NNODES / 4; i += 128)
        ((float4*)dem_s)[i] = ((const float4*)demands)[i];

    // thread owns nodes k = (i*128 + t)*4 + c,  i in 0..3, c in 0..3
    float4 u4[4];
#pragma unroll
    for (int i = 0; i < 4; i++)
        u4[i] = ((const float4*)g_u)[i * 128 + t];
    __syncthreads();
    float4 dm4[4];
#pragma unroll
    for (int i = 0; i < 4; i++)
        dm4[i] = ((const float4*)dem_s)[i * 128 + t];

    unsigned vis = 0;                  // bit (i*4+c)
    if (((depot >> 2) & 127) == t) vis |= 1u << (((depot >> 9) << 2) + (depot & 3));
    if (t == 0) out[0] = (float)depot;

    float loadv  = capf;
    int   done   = 0;
    int   vcount = 1;

    // pipeline prologue: load depot row
    float4 st[4];
    {
        const float4* row = (const float4*)(g_ST + (size_t)depot * NNODES);
#pragma unroll
        for (int i = 0; i < 4; i++) st[i] = row[i * 128 + t];
    }

    for (int step = 0; step < TSTEPS; step++) {
        const int p = step & 1;
        const float lf = loadv * inv_cap;

        // masked scores for the 16 owned nodes (st loaded last iteration)
        float m[16];
#pragma unroll
        for (int i = 0; i < 4; i++) {
            const float* sp = (const float*)&st[i];
            const float* up = (const float*)&u4[i];
            const float* dp = (const float*)&dm4[i];
#pragma unroll
            for (int c = 0; c < 4; c++) {
                float s = fmaf(up[c], lf, sp[c]);
                bool feas = (((vis >> (i * 4 + c)) & 1u) == 0u) && (dp[c] <= loadv);
                m[i * 4 + c] = feas ? s : -CUDART_INF_F;
            }
        }

        // local value max (balanced fmax tree)
        float p8[8];
#pragma unroll
        for (int i = 0; i < 8; i++) p8[i] = fmaxf(m[i], m[i + 8]);
        float p4a = fmaxf(p8[0], p8[4]), p4b = fmaxf(p8[1], p8[5]);
        float p4c = fmaxf(p8[2], p8[6]), p4d = fmaxf(p8[3], p8[7]);
        float lmax = fmaxf(fmaxf(p4a, p4b), fmaxf(p4c, p4d));

        // per-warp value winner
        unsigned wmax = __reduce_max_sync(0xffffffffu, mapf(lmax));
        const unsigned wraw = unmapf(wmax);

        // per-warp min index matching the warp winner value
        int li = 0x7fffffff;
#pragma unroll
        for (int i = 0; i < 4; i++)
#pragma unroll
            for (int c = 0; c < 4; c++) {
                int k = ((i * 128 + t) << 2) + c;
                int cand = (__float_as_uint(m[i * 4 + c]) == wraw) ? k : 0x7fffffff;
                li = min(li, cand);
            }
        unsigned wmin = __reduce_min_sync(0xffffffffu, (unsigned)li);

        if (lane == 0)
            wkey[p][wid] = ((unsigned long long)wmax << 32) | (unsigned)(~wmin);
        __syncthreads();   // the ONLY barrier per step (parity buffer kills the WAR)

        // merge 4 warp keys: 64-bit max == lexicographic (max value, min index)
        const ulonglong2 k01 = ((const ulonglong2*)wkey[p])[0];
        const ulonglong2 k23 = ((const ulonglong2*)wkey[p])[1];
        unsigned long long bestk = max(max(k01.x, k01.y), max(k23.x, k23.y));

        const unsigned gbits = unmapf((unsigned)(bestk >> 32));
        const float bv = __uint_as_float(gbits);
        const int   bi = (int)~((unsigned)bestk);

        const int take = (bv != -CUDART_INF_F) && !done;
        const int nxt  = take ? bi : depot;

        // ---- issue next row's loads FIRST: everything below runs in their shadow
        const float4* nrow = (const float4*)(g_ST + (size_t)nxt * NNODES);
        float4 n0 = nrow[t];
        float4 n1 = nrow[128 + t];
        float4 n2 = nrow[256 + t];
        float4 n3 = nrow[384 + t];

        if (t == 0) {
            out[1 + step]            = (float)nxt;
            out[(TSTEPS + 1) + step] = take ? bv : 0.0f;
        }

        if (take) {
            if (((bi >> 2) & 127) == t) vis |= 1u << (((bi >> 9) << 2) + (bi & 3));
            loadv = loadv - dem_s[bi];
            vcount++;
        } else {
            loadv = capf;
        }
        done = done || (!take && vcount == NNODES);

        if (done) {
            // remaining steps are pure padding: depot / score 0
            const float df = (float)depot;
            for (int j = step + 1 + t; j < TSTEPS; j += 128) {
                out[1 + j]            = df;
                out[(TSTEPS + 1) + j] = 0.0f;
            }
            break;
        }

        st[0] = n0; st[1] = n1; st[2] = n2; st[3] = n3;
    }
}

// ---------------------------------------------------------------------------
extern "C" void kernel_launch(void* const* d_in, const int* in_sizes, int n_in,
                              void* d_out, int out_size)
{
    const float* node_emb = (const float*)d_in[0];   // [2048,1024]
    const float* demands  = (const float*)d_in[1];   // [2048]
    const float* Wq       = (const float*)d_in[2];   // [1024,1026]
    const float* bq       = (const float*)d_in[3];   // [1024]
    const float* Wk       = (const float*)d_in[4];   // [1024,1024]
    const float* bk       = (const float*)d_in[5];   // [1024]
    const int*   cap_p    = (const int*)d_in[6];     // scalar 40
    const int*   depot_p  = (const int*)d_in[7];     // scalar 0
    float* out = (float*)d_out;

    const float SC = 0.015625f;  // ALPHA / sqrt(HID)

    void *pK, *pWqT, *pB, *pST, *pW0;
    cudaGetSymbolAddress(&pK,   g_K);
    cudaGetSymbolAddress(&pWqT, g_WqT);
    cudaGetSymbolAddress(&pB,   g_B);
    cudaGetSymbolAddress(&pST,  g_ST);
    cudaGetSymbolAddress(&pW0,  g_w0);

    // 1) K = node_emb @ Wk^T + bk
    sgemm_nt<<<dim3(HID / 128, NNODES / 128), 256>>>(
        node_emb, HID, Wk, HID, (float*)pK, HID, NNODES, HID, HID, bk, 1.0f);

    // 2) WqT = Wq^T
    transpose_kernel<<<dim3((HID + 2 + 31) / 32, (HID + 31) / 32), dim3(32, 32)>>>(
        Wq, (float*)pWqT, HID, HID + 2);

    // 3) B = K @ Wq   ([2048,1026], ld 1028)
    sgemm_nt<<<dim3((HID + 2 + 127) / 128, NNODES / 128), 256>>>(
        (const float*)pK, HID, (const float*)pWqT, HID,
        (float*)pB, LDB_B, NNODES, HID + 2, HID, nullptr, 1.0f);

    // 4) w0 = K @ bq ; u' = SC * B[:,HID]
    uw_kernel<<<NNODES / 8, 256>>>(bq);

    // 5) ST' = SC * (node_emb @ B[:, :HID]^T + w0)   ([2048,2048])
    sgemm_nt<<<dim3(NNODES / 128, NNODES / 128), 256>>>(
        node_emb, HID, (const float*)pB, LDB_B,
        (float*)pST, NNODES, NNODES, NNODES, HID, (const float*)pW0, SC);

    // 6) re-stream ST through L2 so decode's row loads are L2 hits (R10 WIN)
    warm_l2_kernel<<<2048, 256>>>();

    // 7) sequential decode (single CTA, 4 warps, pipelined row loads)
    decode_kernel<<<1, 128>>>(demands, cap_p, depot_p, out);
}